// round 15
// baseline (speedup 1.0000x reference)
#include <cuda_runtime.h>

#define BB      32
#define HQ      32
#define HKV     8
#define D       128
#define T       2048
#define G       4            // HQ / HKV
#define SCALING 0.08838834764831845f
#define NTHREADS 256
#define NWARPS   8
#define CHUNK   128
#define NSPLIT  (T / CHUNK)  // 16
#define FULLM   0xffffffffu

// split-T scratch: partial unnormalized O (shift m=30 fixed) and per-g sum
__device__ float g_po[BB * HKV * NSPLIT * G * D];   // 8 MB
__device__ float g_s [BB * HKV * NSPLIT * G];       // 64 KB
__device__ int   g_cnt[BB * HKV];                    // ticket counters (zero-init)

__device__ __forceinline__ int load_seqlen(const void* seq_lens, int b) {
    const unsigned* w = (const unsigned*)seq_lens;
    if (w[1] == 0u) return (int)((const long long*)seq_lens)[b];   // int64 storage
    return ((const int*)seq_lens)[b];                              // int32 storage
}

// p = exp(30*tanh(x/30) - 30) = exp(-60 / (exp(x/15) + 1))
// exact softmax numerator under the fixed shift m=30 (logits are capped at 30).
__device__ __forceinline__ float capped_exp(float x) {
    float u = __expf(x * (1.0f / 15.0f));
    return __expf(__fdividef(-60.0f, u + 1.0f));
}

__device__ __forceinline__ void prefetch_l2(const void* p) {
    asm volatile("prefetch.global.L2 [%0];" :: "l"(p));
}

__global__ __launch_bounds__(NTHREADS) void radix_attn_fused(
    const float* __restrict__ q,
    const float* __restrict__ knew,
    const float* __restrict__ vnew,
    const float* __restrict__ kbuf,
    const float* __restrict__ vbuf,
    const void*  __restrict__ seq_lens,
    float* __restrict__ out)
{
    const int h    = blockIdx.x;   // kv head
    const int b    = blockIdx.y;   // batch
    const int c    = blockIdx.z;   // T-split
    const int tid  = threadIdx.x;
    const int lane = tid & 31;
    const int warp = tid >> 5;

    const int L  = load_seqlen(seq_lens, b);
    const int t0 = c * CHUNK;
    if (t0 >= L) return;                     // inactive split
    const int tend = min(L, t0 + CHUNK);

    // does this chunk contain the fresh-token row L-1?
    const bool has_last = (c == ((L - 1) >> 7));       // CHUNK = 128
    const int  tendLoop = has_last ? tend - 1 : tend;  // loop covers buffer rows only

    // lane-role constants for the diagonal-select reduction (g = lane&3)
    const bool l1    = (lane & 1) != 0;
    const bool l2    = (lane & 2) != 0;
    const int  baseg = lane & 28;

    // ---- per-lane query fragments (float4 per g) ----
    float4 qv[G];
#pragma unroll
    for (int g = 0; g < G; g++)
        qv[g] = ((const float4*)(q + ((size_t)b * HQ + (size_t)h * G + g) * D))[lane];

    float4 acc[G];
#pragma unroll
    for (int g = 0; g < G; g++) acc[g] = make_float4(0.f, 0.f, 0.f, 0.f);
    float sum[G] = {0.f, 0.f, 0.f, 0.f};

    const size_t rowstride = (size_t)HKV * D;          // floats per token
    // ---- single fused pass over buffer rows: 2 rows/iter, strided walk ----
    int t = t0 + warp;
    for (; t + NWARPS < tendLoop; t += 2 * NWARPS) {
        const size_t r1 = ((size_t)(b * T + t) * HKV + h) * D;
        const size_t r2 = r1 + (size_t)NWARPS * rowstride;
        // 4 independent loads in flight; evict-first (no reuse)
        float4 kv1 = __ldcs((const float4*)(kbuf + r1) + lane);
        float4 kv2 = __ldcs((const float4*)(kbuf + r2) + lane);
        float4 vv1 = __ldcs((const float4*)(vbuf + r1) + lane);
        float4 vv2 = __ldcs((const float4*)(vbuf + r2) + lane);

        // L2 prefetch for the NEXT iteration (no registers consumed)
        if (t + 3 * NWARPS < tendLoop) {
            const size_t r1n = r1 + (size_t)(2 * NWARPS) * rowstride;
            const size_t r2n = r1 + (size_t)(3 * NWARPS) * rowstride;
            prefetch_l2((const float4*)(kbuf + r1n) + lane);
            prefetch_l2((const float4*)(kbuf + r2n) + lane);
            prefetch_l2((const float4*)(vbuf + r1n) + lane);
            prefetch_l2((const float4*)(vbuf + r2n) + lane);
        }

        float a1[G], a2[G];
#pragma unroll
        for (int g = 0; g < G; g++) {
            a1[g] = kv1.x * qv[g].x + kv1.y * qv[g].y + kv1.z * qv[g].z + kv1.w * qv[g].w;
            a2[g] = kv2.x * qv[g].x + kv2.y * qv[g].y + kv2.z * qv[g].z + kv2.w * qv[g].w;
        }
        // stage A: reduce lane bits 0,1 (4-lane groups; classes = bits 2,3,4)
#pragma unroll
        for (int g = 0; g < G; g++) {
            a1[g] += __shfl_xor_sync(FULLM, a1[g], 1);
            a1[g] += __shfl_xor_sync(FULLM, a1[g], 2);
            a2[g] += __shfl_xor_sync(FULLM, a2[g], 1);
            a2[g] += __shfl_xor_sync(FULLM, a2[g], 2);
        }
        // diagonal select: this lane carries g = lane&3 from here on
        float w1 = l2 ? (l1 ? a1[3] : a1[2]) : (l1 ? a1[1] : a1[0]);
        float w2 = l2 ? (l1 ? a2[3] : a2[2]) : (l1 ? a2[1] : a2[0]);
        // stage B: sum the 8 groups (bits 2,3,4)
        w1 += __shfl_xor_sync(FULLM, w1, 4);
        w2 += __shfl_xor_sync(FULLM, w2, 4);
        w1 += __shfl_xor_sync(FULLM, w1, 8);
        w2 += __shfl_xor_sync(FULLM, w2, 8);
        w1 += __shfl_xor_sync(FULLM, w1, 16);
        w2 += __shfl_xor_sync(FULLM, w2, 16);
        // ONE exp sequence per row covers all 4 g (one g per lane)
        float p1 = capped_exp(w1 * SCALING);
        float p2 = capped_exp(w2 * SCALING);
        // broadcast p[g] to every lane
        float p1g[G], p2g[G];
#pragma unroll
        for (int g = 0; g < G; g++) {
            p1g[g] = __shfl_sync(FULLM, p1, baseg | g);
            p2g[g] = __shfl_sync(FULLM, p2, baseg | g);
        }
#pragma unroll
        for (int g = 0; g < G; g++) {
            sum[g] += p1g[g] + p2g[g];
            acc[g].x += p1g[g] * vv1.x + p2g[g] * vv2.x;
            acc[g].y += p1g[g] * vv1.y + p2g[g] * vv2.y;
            acc[g].z += p1g[g] * vv1.z + p2g[g] * vv2.z;
            acc[g].w += p1g[g] * vv1.w + p2g[g] * vv2.w;
        }
    }
    if (t < tendLoop) {                      // remainder buffer row
        const size_t r = ((size_t)(b * T + t) * HKV + h) * D;
        float4 kv = __ldcs((const float4*)(kbuf + r) + lane);
        float4 vv = __ldcs((const float4*)(vbuf + r) + lane);
        float a[G];
#pragma unroll
        for (int g = 0; g < G; g++) {
            a[g] = kv.x * qv[g].x + kv.y * qv[g].y + kv.z * qv[g].z + kv.w * qv[g].w;
            a[g] += __shfl_xor_sync(FULLM, a[g], 1);
            a[g] += __shfl_xor_sync(FULLM, a[g], 2);
        }
        float w = l2 ? (l1 ? a[3] : a[2]) : (l1 ? a[1] : a[0]);
        w += __shfl_xor_sync(FULLM, w, 4);
        w += __shfl_xor_sync(FULLM, w, 8);
        w += __shfl_xor_sync(FULLM, w, 16);
        float p = capped_exp(w * SCALING);
#pragma unroll
        for (int g = 0; g < G; g++) {
            float pg = __shfl_sync(FULLM, p, baseg | g);
            sum[g] += pg;
            acc[g].x += pg * vv.x;
            acc[g].y += pg * vv.y;
            acc[g].z += pg * vv.z;
            acc[g].w += pg * vv.w;
        }
    }
    if (has_last && warp == 0) {             // fresh-token row L-1, once per CTA
        const float4* kr = (const float4*)(knew + ((size_t)b * HKV + h) * D);
        const float4* vr = (const float4*)(vnew + ((size_t)b * HKV + h) * D);
        float4 kv = kr[lane];
        float4 vv = vr[lane];
        float a[G];
#pragma unroll
        for (int g = 0; g < G; g++) {
            a[g] = kv.x * qv[g].x + kv.y * qv[g].y + kv.z * qv[g].z + kv.w * qv[g].w;
            a[g] += __shfl_xor_sync(FULLM, a[g], 1);
            a[g] += __shfl_xor_sync(FULLM, a[g], 2);
        }
        float w = l2 ? (l1 ? a[3] : a[2]) : (l1 ? a[1] : a[0]);
        w += __shfl_xor_sync(FULLM, w, 4);
        w += __shfl_xor_sync(FULLM, w, 8);
        w += __shfl_xor_sync(FULLM, w, 16);
        float p = capped_exp(w * SCALING);
#pragma unroll
        for (int g = 0; g < G; g++) {
            float pg = __shfl_sync(FULLM, p, baseg | g);
            sum[g] += pg;
            acc[g].x += pg * vv.x;
            acc[g].y += pg * vv.y;
            acc[g].z += pg * vv.z;
            acc[g].w += pg * vv.w;
        }
    }

    // ---- cross-warp reduce in smem ----
    __shared__ float sO[NWARPS * G * D];     // 16 KB
    __shared__ float sS[NWARPS * G];
#pragma unroll
    for (int g = 0; g < G; g++)
        ((float4*)&sO[(warp * G + g) * D])[lane] = acc[g];
    if (lane == 0) {
#pragma unroll
        for (int g = 0; g < G; g++) sS[warp * G + g] = sum[g];
    }
    __syncthreads();

    const int    bh   = b * HKV + h;
    const size_t base = ((size_t)bh * NSPLIT + c) * G;
    for (int i = tid; i < G * D; i += NTHREADS) {
        float v = 0.f;
#pragma unroll
        for (int w2_ = 0; w2_ < NWARPS; w2_++) v += sO[w2_ * G * D + i];
        g_po[base * D + i] = v;
    }
    if (tid < G) {
        float s = 0.f;
#pragma unroll
        for (int w2_ = 0; w2_ < NWARPS; w2_++) s += sS[w2_ * G + tid];
        g_s[base + tid] = s;
    }

    // ---- atomic ticket: last CTA of this (b,h) combines (scratch L2-hot) ----
    const int NS = (L + CHUNK - 1) / CHUNK;  // number of active chunks
    __shared__ int sTicket;
    __threadfence();                         // publish scratch before ticket
    __syncthreads();                         // all scratch stores issued
    if (tid == 0) sTicket = atomicAdd(&g_cnt[bh], 1);
    __syncthreads();
    if (sTicket != NS - 1) return;           // not the last: done

    if (tid == 0) g_cnt[bh] = 0;             // reset for next graph replay
    __threadfence();                         // acquire side

    __shared__ float sInv[G];
    if (tid < G) {
        float S = 0.f;
        for (int c2 = 0; c2 < NS; c2++)
            S += __ldcg(&g_s[((size_t)bh * NSPLIT + c2) * G + tid]);
        sInv[tid] = 1.0f / S;
    }
    __syncthreads();

    // 256 threads produce 512 outputs (2 each); reads are L2-hot
    for (int i = tid; i < G * D; i += NTHREADS) {
        const int g = i >> 7, d = i & 127;
        float o = 0.f;
        for (int c2 = 0; c2 < NS; c2++)
            o += __ldcg(&g_po[((size_t)bh * NSPLIT + c2) * G * D + i]);
        out[((size_t)b * HQ + (size_t)h * G + g) * D + d] = o * sInv[g];
    }
}

extern "C" void kernel_launch(void* const* d_in, const int* in_sizes, int n_in,
                              void* d_out, int out_size)
{
    const float* q    = (const float*)d_in[0];
    const float* k    = (const float*)d_in[1];
    const float* v    = (const float*)d_in[2];
    const float* kbuf = (const float*)d_in[3];
    const float* vbuf = (const float*)d_in[4];
    const void*  seq  = d_in[7];

    dim3 grid(HKV, BB, NSPLIT);
    radix_attn_fused<<<grid, NTHREADS>>>(q, k, v, kbuf, vbuf, seq, (float*)d_out);
}

// round 16
// speedup vs baseline: 1.1807x; 1.1807x over previous
#include <cuda_runtime.h>

#define BB      32
#define HQ      32
#define HKV     8
#define D       128
#define T       2048
#define G       4            // HQ / HKV
#define SCALING 0.08838834764831845f
#define NTHREADS 256
#define NWARPS   8
#define CHUNK   128
#define NSPLIT  (T / CHUNK)  // 16
#define FULLM   0xffffffffu

// split-T scratch: partial unnormalized O (shift m=30 fixed) and per-g sum
__device__ float g_po[BB * HKV * NSPLIT * G * D];   // 8 MB
__device__ float g_s [BB * HKV * NSPLIT * G];       // 64 KB

__device__ __forceinline__ int load_seqlen(const void* seq_lens, int b) {
    const unsigned* w = (const unsigned*)seq_lens;
    if (w[1] == 0u) return (int)((const long long*)seq_lens)[b];   // int64 storage
    return ((const int*)seq_lens)[b];                              // int32 storage
}

// p = exp(30*tanh(x/30) - 30) = exp(-60 / (exp(x/15) + 1))
// exact softmax numerator under the fixed shift m=30 (logits are capped at 30).
__device__ __forceinline__ float capped_exp(float x) {
    float u = __expf(x * (1.0f / 15.0f));
    return __expf(__fdividef(-60.0f, u + 1.0f));
}

__device__ __forceinline__ void prefetch_l2(const void* p) {
    asm volatile("prefetch.global.L2 [%0];" :: "l"(p));
}

__global__ void __launch_bounds__(NTHREADS, 4) radix_attn_partial(
    const float* __restrict__ q,
    const float* __restrict__ knew,
    const float* __restrict__ vnew,
    const float* __restrict__ kbuf,
    const float* __restrict__ vbuf,
    const void*  __restrict__ seq_lens)
{
    const int h    = blockIdx.x;   // kv head
    const int b    = blockIdx.y;   // batch
    const int c    = blockIdx.z;   // T-split
    const int tid  = threadIdx.x;
    const int lane = tid & 31;
    const int warp = tid >> 5;

    const int L  = load_seqlen(seq_lens, b);
    const int t0 = c * CHUNK;
    if (t0 >= L) return;                     // inactive split
    const int tend = min(L, t0 + CHUNK);

    // does this chunk contain the fresh-token row L-1?
    const bool has_last = (c == ((L - 1) >> 7));       // CHUNK = 128
    const int  tendLoop = has_last ? tend - 1 : tend;  // loop covers buffer rows only

    // lane-role constants for the diagonal-select reduction (g = lane&3)
    const bool l1    = (lane & 1) != 0;
    const bool l2    = (lane & 2) != 0;
    const int  baseg = lane & 28;

    // ---- per-lane query fragments (float4 per g) ----
    float4 qv[G];
#pragma unroll
    for (int g = 0; g < G; g++)
        qv[g] = ((const float4*)(q + ((size_t)b * HQ + (size_t)h * G + g) * D))[lane];

    float4 acc[G];
#pragma unroll
    for (int g = 0; g < G; g++) acc[g] = make_float4(0.f, 0.f, 0.f, 0.f);
    float sum[G] = {0.f, 0.f, 0.f, 0.f};

    const size_t rowstride = (size_t)HKV * D;          // floats per token
    // ---- single fused pass over buffer rows: 2 rows/iter, strided walk ----
    int t = t0 + warp;
    for (; t + NWARPS < tendLoop; t += 2 * NWARPS) {
        const size_t r1 = ((size_t)(b * T + t) * HKV + h) * D;
        const size_t r2 = r1 + (size_t)NWARPS * rowstride;
        // 4 independent loads in flight; evict-first (no reuse)
        float4 kv1 = __ldcs((const float4*)(kbuf + r1) + lane);
        float4 kv2 = __ldcs((const float4*)(kbuf + r2) + lane);
        float4 vv1 = __ldcs((const float4*)(vbuf + r1) + lane);
        float4 vv2 = __ldcs((const float4*)(vbuf + r2) + lane);

        // L2 prefetch for the NEXT iteration (no registers consumed)
        if (t + 3 * NWARPS < tendLoop) {
            const size_t r1n = r1 + (size_t)(2 * NWARPS) * rowstride;
            const size_t r2n = r1 + (size_t)(3 * NWARPS) * rowstride;
            prefetch_l2((const float4*)(kbuf + r1n) + lane);
            prefetch_l2((const float4*)(kbuf + r2n) + lane);
            prefetch_l2((const float4*)(vbuf + r1n) + lane);
            prefetch_l2((const float4*)(vbuf + r2n) + lane);
        }

        float a1[G], a2[G];
#pragma unroll
        for (int g = 0; g < G; g++) {
            a1[g] = kv1.x * qv[g].x + kv1.y * qv[g].y + kv1.z * qv[g].z + kv1.w * qv[g].w;
            a2[g] = kv2.x * qv[g].x + kv2.y * qv[g].y + kv2.z * qv[g].z + kv2.w * qv[g].w;
        }
        // stage A: reduce lane bits 0,1 (4-lane groups; classes = bits 2,3,4)
#pragma unroll
        for (int g = 0; g < G; g++) {
            a1[g] += __shfl_xor_sync(FULLM, a1[g], 1);
            a1[g] += __shfl_xor_sync(FULLM, a1[g], 2);
            a2[g] += __shfl_xor_sync(FULLM, a2[g], 1);
            a2[g] += __shfl_xor_sync(FULLM, a2[g], 2);
        }
        // diagonal select: this lane carries g = lane&3 from here on
        float w1 = l2 ? (l1 ? a1[3] : a1[2]) : (l1 ? a1[1] : a1[0]);
        float w2 = l2 ? (l1 ? a2[3] : a2[2]) : (l1 ? a2[1] : a2[0]);
        // stage B: sum the 8 groups (bits 2,3,4)
        w1 += __shfl_xor_sync(FULLM, w1, 4);
        w2 += __shfl_xor_sync(FULLM, w2, 4);
        w1 += __shfl_xor_sync(FULLM, w1, 8);
        w2 += __shfl_xor_sync(FULLM, w2, 8);
        w1 += __shfl_xor_sync(FULLM, w1, 16);
        w2 += __shfl_xor_sync(FULLM, w2, 16);
        // ONE exp sequence per row covers all 4 g (one g per lane)
        float p1 = capped_exp(w1 * SCALING);
        float p2 = capped_exp(w2 * SCALING);
        // broadcast p[g] to every lane
        float p1g[G], p2g[G];
#pragma unroll
        for (int g = 0; g < G; g++) {
            p1g[g] = __shfl_sync(FULLM, p1, baseg | g);
            p2g[g] = __shfl_sync(FULLM, p2, baseg | g);
        }
#pragma unroll
        for (int g = 0; g < G; g++) {
            sum[g] += p1g[g] + p2g[g];
            acc[g].x += p1g[g] * vv1.x + p2g[g] * vv2.x;
            acc[g].y += p1g[g] * vv1.y + p2g[g] * vv2.y;
            acc[g].z += p1g[g] * vv1.z + p2g[g] * vv2.z;
            acc[g].w += p1g[g] * vv1.w + p2g[g] * vv2.w;
        }
    }
    if (t < tendLoop) {                      // remainder buffer row
        const size_t r = ((size_t)(b * T + t) * HKV + h) * D;
        float4 kv = __ldcs((const float4*)(kbuf + r) + lane);
        float4 vv = __ldcs((const float4*)(vbuf + r) + lane);
        float a[G];
#pragma unroll
        for (int g = 0; g < G; g++) {
            a[g] = kv.x * qv[g].x + kv.y * qv[g].y + kv.z * qv[g].z + kv.w * qv[g].w;
            a[g] += __shfl_xor_sync(FULLM, a[g], 1);
            a[g] += __shfl_xor_sync(FULLM, a[g], 2);
        }
        float w = l2 ? (l1 ? a[3] : a[2]) : (l1 ? a[1] : a[0]);
        w += __shfl_xor_sync(FULLM, w, 4);
        w += __shfl_xor_sync(FULLM, w, 8);
        w += __shfl_xor_sync(FULLM, w, 16);
        float p = capped_exp(w * SCALING);
#pragma unroll
        for (int g = 0; g < G; g++) {
            float pg = __shfl_sync(FULLM, p, baseg | g);
            sum[g] += pg;
            acc[g].x += pg * vv.x;
            acc[g].y += pg * vv.y;
            acc[g].z += pg * vv.z;
            acc[g].w += pg * vv.w;
        }
    }
    if (has_last && warp == 0) {             // fresh-token row L-1, once per CTA
        const float4* kr = (const float4*)(knew + ((size_t)b * HKV + h) * D);
        const float4* vr = (const float4*)(vnew + ((size_t)b * HKV + h) * D);
        float4 kv = kr[lane];
        float4 vv = vr[lane];
        float a[G];
#pragma unroll
        for (int g = 0; g < G; g++) {
            a[g] = kv.x * qv[g].x + kv.y * qv[g].y + kv.z * qv[g].z + kv.w * qv[g].w;
            a[g] += __shfl_xor_sync(FULLM, a[g], 1);
            a[g] += __shfl_xor_sync(FULLM, a[g], 2);
        }
        float w = l2 ? (l1 ? a[3] : a[2]) : (l1 ? a[1] : a[0]);
        w += __shfl_xor_sync(FULLM, w, 4);
        w += __shfl_xor_sync(FULLM, w, 8);
        w += __shfl_xor_sync(FULLM, w, 16);
        float p = capped_exp(w * SCALING);
#pragma unroll
        for (int g = 0; g < G; g++) {
            float pg = __shfl_sync(FULLM, p, baseg | g);
            sum[g] += pg;
            acc[g].x += pg * vv.x;
            acc[g].y += pg * vv.y;
            acc[g].z += pg * vv.z;
            acc[g].w += pg * vv.w;
        }
    }

    // ---- cross-warp reduce in smem ----
    __shared__ float sO[NWARPS * G * D];     // 16 KB
    __shared__ float sS[NWARPS * G];
#pragma unroll
    for (int g = 0; g < G; g++)
        ((float4*)&sO[(warp * G + g) * D])[lane] = acc[g];
    if (lane == 0) {
#pragma unroll
        for (int g = 0; g < G; g++) sS[warp * G + g] = sum[g];
    }
    __syncthreads();

    const size_t base = ((size_t)(b * HKV + h) * NSPLIT + c) * G;
    for (int i = tid; i < G * D; i += NTHREADS) {
        float v = 0.f;
#pragma unroll
        for (int w2_ = 0; w2_ < NWARPS; w2_++) v += sO[w2_ * G * D + i];
        g_po[base * D + i] = v;
    }
    if (tid < G) {
        float s = 0.f;
#pragma unroll
        for (int w2_ = 0; w2_ < NWARPS; w2_++) s += sS[w2_ * G + tid];
        g_s[base + tid] = s;
    }
}

__global__ __launch_bounds__(512) void radix_attn_combine(
    const void* __restrict__ seq_lens,
    float* __restrict__ out)
{
    const int bh  = blockIdx.x;      // b*HKV + h
    const int b   = bh >> 3;
    const int h   = bh & 7;
    const int tid = threadIdx.x;
    const int g   = tid >> 7;        // 0..3
    const int d   = tid & 127;

    const int L  = load_seqlen(seq_lens, b);
    const int NS = (L + CHUNK - 1) / CHUNK;

    __shared__ float sS[NSPLIT * G];
    const size_t sbase = (size_t)bh * NSPLIT * G;
    for (int i = tid; i < NS * G; i += 512) sS[i] = g_s[sbase + i];
    __syncthreads();

    float S = 0.f;
#pragma unroll
    for (int c = 0; c < NSPLIT; c++)
        if (c < NS) S += sS[c * G + g];

    const size_t pobase = (size_t)bh * NSPLIT * G * D;
    float o = 0.f;
#pragma unroll
    for (int c = 0; c < NSPLIT; c++)       // 16 independent predicated loads
        if (c < NS) o += g_po[pobase + (c * G + g) * D + d];

    out[((size_t)b * HQ + (size_t)h * G + g) * D + d] = o * (1.0f / S);
}

extern "C" void kernel_launch(void* const* d_in, const int* in_sizes, int n_in,
                              void* d_out, int out_size)
{
    const float* q    = (const float*)d_in[0];
    const float* k    = (const float*)d_in[1];
    const float* v    = (const float*)d_in[2];
    const float* kbuf = (const float*)d_in[3];
    const float* vbuf = (const float*)d_in[4];
    const void*  seq  = d_in[7];

    dim3 grid1(HKV, BB, NSPLIT);
    radix_attn_partial<<<grid1, NTHREADS>>>(q, k, v, kbuf, vbuf, seq);
    radix_attn_combine<<<BB * HKV, 512>>>(seq, (float*)d_out);
}

// round 17
// speedup vs baseline: 1.1829x; 1.0018x over previous
#include <cuda_runtime.h>

#define BB      32
#define HQ      32
#define HKV     8
#define D       128
#define T       2048
#define G       4            // HQ / HKV
#define SCALING 0.08838834764831845f
#define NTHREADS 256
#define NWARPS   8
#define CHUNK   128
#define NSPLIT  (T / CHUNK)  // 16
#define FULLM   0xffffffffu

// split-T scratch: partial unnormalized O (shift m=30 fixed) and per-g sum
__device__ float g_po[BB * HKV * NSPLIT * G * D];   // 8 MB
__device__ float g_s [BB * HKV * NSPLIT * G];       // 64 KB

__device__ __forceinline__ int load_seqlen(const void* seq_lens, int b) {
    const unsigned* w = (const unsigned*)seq_lens;
    if (w[1] == 0u) return (int)((const long long*)seq_lens)[b];   // int64 storage
    return ((const int*)seq_lens)[b];                              // int32 storage
}

// p = exp(30*tanh(x/30) - 30) = exp(-60 / (exp(x/15) + 1))
// exact softmax numerator under the fixed shift m=30 (logits are capped at 30).
__device__ __forceinline__ float capped_exp(float x) {
    float u = __expf(x * (1.0f / 15.0f));
    return __expf(__fdividef(-60.0f, u + 1.0f));
}

__device__ __forceinline__ void prefetch_l2(const void* p) {
    asm volatile("prefetch.global.L2 [%0];" :: "l"(p));
}

__global__ void __launch_bounds__(NTHREADS, 4) radix_attn_partial(
    const float* __restrict__ q,
    const float* __restrict__ knew,
    const float* __restrict__ vnew,
    const float* __restrict__ kbuf,
    const float* __restrict__ vbuf,
    const void*  __restrict__ seq_lens)
{
    const int h    = blockIdx.x;   // kv head
    const int b    = blockIdx.y;   // batch
    const int c    = blockIdx.z;   // T-split
    const int tid  = threadIdx.x;
    const int lane = tid & 31;
    const int warp = tid >> 5;

    const int L  = load_seqlen(seq_lens, b);
    const int t0 = c * CHUNK;
    if (t0 >= L) return;                     // inactive split
    const int tend = min(L, t0 + CHUNK);

    // does this chunk contain the fresh-token row L-1?
    const bool has_last = (c == ((L - 1) >> 7));       // CHUNK = 128
    const int  tendLoop = has_last ? tend - 1 : tend;  // loop covers buffer rows only

    // lane-role constants for the diagonal-select reduction (g = lane&3)
    const bool l1    = (lane & 1) != 0;
    const bool l2    = (lane & 2) != 0;
    const int  baseg = lane & 28;

    // ---- per-lane query fragments (float4 per g) ----
    float4 qv[G];
#pragma unroll
    for (int g = 0; g < G; g++)
        qv[g] = ((const float4*)(q + ((size_t)b * HQ + (size_t)h * G + g) * D))[lane];

    float4 acc[G];
#pragma unroll
    for (int g = 0; g < G; g++) acc[g] = make_float4(0.f, 0.f, 0.f, 0.f);
    float sum[G] = {0.f, 0.f, 0.f, 0.f};

    const size_t rowstride = (size_t)HKV * D;          // floats per token
    // ---- single fused pass over buffer rows: 2 rows/iter, strided walk ----
    int t = t0 + warp;
    for (; t + NWARPS < tendLoop; t += 2 * NWARPS) {
        const size_t r1 = ((size_t)(b * T + t) * HKV + h) * D;
        const size_t r2 = r1 + (size_t)NWARPS * rowstride;
        // 4 independent loads in flight; evict-first (no reuse)
        float4 kv1 = __ldcs((const float4*)(kbuf + r1) + lane);
        float4 kv2 = __ldcs((const float4*)(kbuf + r2) + lane);
        float4 vv1 = __ldcs((const float4*)(vbuf + r1) + lane);
        float4 vv2 = __ldcs((const float4*)(vbuf + r2) + lane);

        // L2 prefetch for the NEXT iteration (no registers consumed)
        if (t + 3 * NWARPS < tendLoop) {
            const size_t r1n = r1 + (size_t)(2 * NWARPS) * rowstride;
            const size_t r2n = r1 + (size_t)(3 * NWARPS) * rowstride;
            prefetch_l2((const float4*)(kbuf + r1n) + lane);
            prefetch_l2((const float4*)(kbuf + r2n) + lane);
            prefetch_l2((const float4*)(vbuf + r1n) + lane);
            prefetch_l2((const float4*)(vbuf + r2n) + lane);
        }

        float a1[G], a2[G];
#pragma unroll
        for (int g = 0; g < G; g++) {
            a1[g] = kv1.x * qv[g].x + kv1.y * qv[g].y + kv1.z * qv[g].z + kv1.w * qv[g].w;
            a2[g] = kv2.x * qv[g].x + kv2.y * qv[g].y + kv2.z * qv[g].z + kv2.w * qv[g].w;
        }
        // stage A: reduce lane bits 0,1 (4-lane groups; classes = bits 2,3,4)
#pragma unroll
        for (int g = 0; g < G; g++) {
            a1[g] += __shfl_xor_sync(FULLM, a1[g], 1);
            a1[g] += __shfl_xor_sync(FULLM, a1[g], 2);
            a2[g] += __shfl_xor_sync(FULLM, a2[g], 1);
            a2[g] += __shfl_xor_sync(FULLM, a2[g], 2);
        }
        // diagonal select: this lane carries g = lane&3 from here on
        float w1 = l2 ? (l1 ? a1[3] : a1[2]) : (l1 ? a1[1] : a1[0]);
        float w2 = l2 ? (l1 ? a2[3] : a2[2]) : (l1 ? a2[1] : a2[0]);
        // stage B: sum the 8 groups (bits 2,3,4)
        w1 += __shfl_xor_sync(FULLM, w1, 4);
        w2 += __shfl_xor_sync(FULLM, w2, 4);
        w1 += __shfl_xor_sync(FULLM, w1, 8);
        w2 += __shfl_xor_sync(FULLM, w2, 8);
        w1 += __shfl_xor_sync(FULLM, w1, 16);
        w2 += __shfl_xor_sync(FULLM, w2, 16);
        // ONE exp sequence per row covers all 4 g (one g per lane)
        float p1 = capped_exp(w1 * SCALING);
        float p2 = capped_exp(w2 * SCALING);
        // broadcast p[g] to every lane
        float p1g[G], p2g[G];
#pragma unroll
        for (int g = 0; g < G; g++) {
            p1g[g] = __shfl_sync(FULLM, p1, baseg | g);
            p2g[g] = __shfl_sync(FULLM, p2, baseg | g);
        }
#pragma unroll
        for (int g = 0; g < G; g++) {
            sum[g] += p1g[g] + p2g[g];
            acc[g].x += p1g[g] * vv1.x + p2g[g] * vv2.x;
            acc[g].y += p1g[g] * vv1.y + p2g[g] * vv2.y;
            acc[g].z += p1g[g] * vv1.z + p2g[g] * vv2.z;
            acc[g].w += p1g[g] * vv1.w + p2g[g] * vv2.w;
        }
    }
    if (t < tendLoop) {                      // remainder buffer row
        const size_t r = ((size_t)(b * T + t) * HKV + h) * D;
        float4 kv = __ldcs((const float4*)(kbuf + r) + lane);
        float4 vv = __ldcs((const float4*)(vbuf + r) + lane);
        float a[G];
#pragma unroll
        for (int g = 0; g < G; g++) {
            a[g] = kv.x * qv[g].x + kv.y * qv[g].y + kv.z * qv[g].z + kv.w * qv[g].w;
            a[g] += __shfl_xor_sync(FULLM, a[g], 1);
            a[g] += __shfl_xor_sync(FULLM, a[g], 2);
        }
        float w = l2 ? (l1 ? a[3] : a[2]) : (l1 ? a[1] : a[0]);
        w += __shfl_xor_sync(FULLM, w, 4);
        w += __shfl_xor_sync(FULLM, w, 8);
        w += __shfl_xor_sync(FULLM, w, 16);
        float p = capped_exp(w * SCALING);
#pragma unroll
        for (int g = 0; g < G; g++) {
            float pg = __shfl_sync(FULLM, p, baseg | g);
            sum[g] += pg;
            acc[g].x += pg * vv.x;
            acc[g].y += pg * vv.y;
            acc[g].z += pg * vv.z;
            acc[g].w += pg * vv.w;
        }
    }
    if (has_last && warp == 0) {             // fresh-token row L-1, once per CTA
        const float4* kr = (const float4*)(knew + ((size_t)b * HKV + h) * D);
        const float4* vr = (const float4*)(vnew + ((size_t)b * HKV + h) * D);
        float4 kv = kr[lane];
        float4 vv = vr[lane];
        float a[G];
#pragma unroll
        for (int g = 0; g < G; g++) {
            a[g] = kv.x * qv[g].x + kv.y * qv[g].y + kv.z * qv[g].z + kv.w * qv[g].w;
            a[g] += __shfl_xor_sync(FULLM, a[g], 1);
            a[g] += __shfl_xor_sync(FULLM, a[g], 2);
        }
        float w = l2 ? (l1 ? a[3] : a[2]) : (l1 ? a[1] : a[0]);
        w += __shfl_xor_sync(FULLM, w, 4);
        w += __shfl_xor_sync(FULLM, w, 8);
        w += __shfl_xor_sync(FULLM, w, 16);
        float p = capped_exp(w * SCALING);
#pragma unroll
        for (int g = 0; g < G; g++) {
            float pg = __shfl_sync(FULLM, p, baseg | g);
            sum[g] += pg;
            acc[g].x += pg * vv.x;
            acc[g].y += pg * vv.y;
            acc[g].z += pg * vv.z;
            acc[g].w += pg * vv.w;
        }
    }

    // ---- cross-warp reduce in smem ----
    __shared__ float sO[NWARPS * G * D];     // 16 KB
    __shared__ float sS[NWARPS * G];
#pragma unroll
    for (int g = 0; g < G; g++)
        ((float4*)&sO[(warp * G + g) * D])[lane] = acc[g];
    if (lane == 0) {
#pragma unroll
        for (int g = 0; g < G; g++) sS[warp * G + g] = sum[g];
    }
    __syncthreads();

    const size_t base = ((size_t)(b * HKV + h) * NSPLIT + c) * G;
    for (int i = tid; i < G * D; i += NTHREADS) {
        float v = 0.f;
#pragma unroll
        for (int w2_ = 0; w2_ < NWARPS; w2_++) v += sO[w2_ * G * D + i];
        g_po[base * D + i] = v;
    }
    if (tid < G) {
        float s = 0.f;
#pragma unroll
        for (int w2_ = 0; w2_ < NWARPS; w2_++) s += sS[w2_ * G + tid];
        g_s[base + tid] = s;
    }
}

// 128 threads per (b,h); each thread owns one float4 column of O.
__global__ __launch_bounds__(128) void radix_attn_combine(
    const void* __restrict__ seq_lens,
    float* __restrict__ out)
{
    const int bh  = blockIdx.x;      // b*HKV + h
    const int b   = bh >> 3;
    const int h   = bh & 7;
    const int tid = threadIdx.x;     // 0..127: (g = tid>>5, d4 = tid&31)
    const int g   = tid >> 5;

    const int L  = load_seqlen(seq_lens, b);
    const int NS = (L + CHUNK - 1) / CHUNK;

    __shared__ float sS[NSPLIT * G];
    const size_t sbase = (size_t)bh * NSPLIT * G;
    for (int i = tid; i < NS * G; i += 128) sS[i] = g_s[sbase + i];
    __syncthreads();

    float S = 0.f;
#pragma unroll
    for (int c = 0; c < NSPLIT; c++)
        if (c < NS) S += sS[c * G + g];
    const float inv = 1.0f / S;

    const float4* po4 = (const float4*)g_po;
    const size_t  pobase = (size_t)bh * NSPLIT * (G * D / 4);
    float4 o = make_float4(0.f, 0.f, 0.f, 0.f);
#pragma unroll
    for (int c = 0; c < NSPLIT; c++) {       // 16 independent 128-bit loads
        if (c < NS) {
            float4 v = po4[pobase + c * (G * D / 4) + tid];
            o.x += v.x; o.y += v.y; o.z += v.z; o.w += v.w;
        }
    }
    o.x *= inv; o.y *= inv; o.z *= inv; o.w *= inv;
    ((float4*)(out + ((size_t)b * HQ + (size_t)h * G) * D))[tid] = o;
}

extern "C" void kernel_launch(void* const* d_in, const int* in_sizes, int n_in,
                              void* d_out, int out_size)
{
    const float* q    = (const float*)d_in[0];
    const float* k    = (const float*)d_in[1];
    const float* v    = (const float*)d_in[2];
    const float* kbuf = (const float*)d_in[3];
    const float* vbuf = (const float*)d_in[4];
    const void*  seq  = d_in[7];

    dim3 grid1(HKV, BB, NSPLIT);
    radix_attn_partial<<<grid1, NTHREADS>>>(q, k, v, kbuf, vbuf, seq);
    radix_attn_combine<<<BB * HKV, 128>>>(seq, (float*)d_out);
}